// round 1
// baseline (speedup 1.0000x reference)
#include <cuda_runtime.h>

// SAKE GNN, fully fused: one CTA per batch graph (B=512, M=32, H=128, L=2).
// All intermediates live in shared memory; weights staged to SMEM per phase.
// Edge sparsity (d2 < 1, i != j) exploited: pair MLP computed only for real edges.

#define NB   512
#define MM   32
#define HD   128

__device__ __forceinline__ float silu_f(float v) {
    return __fdividef(v, 1.0f + __expf(-v));
}

// cooperative copy of n floats (n % 4 == 0, 16B-aligned) into shared
__device__ __forceinline__ void stage_w(const float* __restrict__ g,
                                        float* __restrict__ sW, int n) {
    for (int idx = threadIdx.x * 4; idx < n; idx += 256 * 4) {
        *(float4*)&sW[idx] = *(const float4*)&g[idx];
    }
}

// acc[rr][c] += sum_{h<nh} X[(i0+rr)*ldx + h] * W[h*128 + k0 + c]
// X rows read as lane-uniform broadcasts; W rows read as conflict-free LDS.128.
__device__ __forceinline__ void gemm_block(const float* __restrict__ sX, int ldx,
                                           const float* __restrict__ sW, int nh,
                                           int i0, int k0, float acc[4][4]) {
    #pragma unroll 4
    for (int h = 0; h < nh; h += 4) {
        float4 w0 = *(const float4*)&sW[(h + 0) * 128 + k0];
        float4 w1 = *(const float4*)&sW[(h + 1) * 128 + k0];
        float4 w2 = *(const float4*)&sW[(h + 2) * 128 + k0];
        float4 w3 = *(const float4*)&sW[(h + 3) * 128 + k0];
        #pragma unroll
        for (int rr = 0; rr < 4; rr++) {
            float4 a = *(const float4*)&sX[(i0 + rr) * ldx + h];
            acc[rr][0] = fmaf(a.x, w0.x, acc[rr][0]);
            acc[rr][0] = fmaf(a.y, w1.x, acc[rr][0]);
            acc[rr][0] = fmaf(a.z, w2.x, acc[rr][0]);
            acc[rr][0] = fmaf(a.w, w3.x, acc[rr][0]);
            acc[rr][1] = fmaf(a.x, w0.y, acc[rr][1]);
            acc[rr][1] = fmaf(a.y, w1.y, acc[rr][1]);
            acc[rr][1] = fmaf(a.z, w2.y, acc[rr][1]);
            acc[rr][1] = fmaf(a.w, w3.y, acc[rr][1]);
            acc[rr][2] = fmaf(a.x, w0.z, acc[rr][2]);
            acc[rr][2] = fmaf(a.y, w1.z, acc[rr][2]);
            acc[rr][2] = fmaf(a.z, w2.z, acc[rr][2]);
            acc[rr][2] = fmaf(a.w, w3.z, acc[rr][2]);
            acc[rr][3] = fmaf(a.x, w0.w, acc[rr][3]);
            acc[rr][3] = fmaf(a.y, w1.w, acc[rr][3]);
            acc[rr][3] = fmaf(a.z, w2.w, acc[rr][3]);
            acc[rr][3] = fmaf(a.w, w3.w, acc[rr][3]);
        }
    }
}

__global__ void __launch_bounds__(256, 1)
sake_kernel(const float* __restrict__ g_h, const float* __restrict__ g_x,
            const float* __restrict__ W_in, const float* __restrict__ b_in,
            const float* __restrict__ We1, const float* __restrict__ be1,
            const float* __restrict__ We2, const float* __restrict__ be2,
            const float* __restrict__ Wh1, const float* __restrict__ bh1,
            const float* __restrict__ Wh2, const float* __restrict__ bh2,
            const float* __restrict__ W_out, const float* __restrict__ b_out,
            const float* __restrict__ Wn1, const float* __restrict__ bn1,
            const float* __restrict__ Wn2, const float* __restrict__ bn2,
            float* __restrict__ g_out)
{
    extern __shared__ float sm[];
    float* s_hg  = sm;                 // 32*128
    float* s_mi  = sm + 4096;          // 32*128
    float* s_mj  = sm + 8192;          // 32*128
    float* s_agg = sm + 12288;         // 32*128
    float* s_W   = sm + 16384;         // 128*128 weight staging
    float* s_d2  = sm + 32768;         // 32*32
    float* s_m1  = sm + 33792;         // 8 warps * 4 rows * 128
    int*   s_jl  = (int*)(sm + 37888); // 8 warps * 32
    float* s_x   = sm + 38144;         // 32*3
    float* s_ht  = sm + 38240;         // 32*16
    float* s_red = sm + 38752;         // 8

    const int tid  = threadIdx.x;
    const int warp = tid >> 5;
    const int lane = tid & 31;
    const int b    = blockIdx.x;
    const int i0   = warp * 4;   // GEMM row base
    const int k0   = lane * 4;   // GEMM col base (also h base in m1 build)

    // ---- load per-batch tiles ----
    if (tid < 96) s_x[tid] = g_x[b * 96 + tid];
    if (tid < 128) *(float4*)&s_ht[tid * 4] = *(const float4*)&g_h[b * 512 + tid * 4];
    stage_w(W_in, s_W, 16 * 128);
    __syncthreads();

    // ---- pairwise squared distances ----
    for (int p = tid; p < 1024; p += 256) {
        int i = p >> 5, j = p & 31;
        float dx = s_x[i * 3 + 0] - s_x[j * 3 + 0];
        float dy = s_x[i * 3 + 1] - s_x[j * 3 + 1];
        float dz = s_x[i * 3 + 2] - s_x[j * 3 + 2];
        s_d2[p] = dx * dx + dy * dy + dz * dz;
    }

    // ---- hg = h @ W_in + b_in ----
    {
        float acc[4][4] = {};
        gemm_block(s_ht, 16, s_W, 16, i0, k0, acc);
        float4 bb = *(const float4*)&b_in[k0];
        #pragma unroll
        for (int rr = 0; rr < 4; rr++) {
            float4 o = { acc[rr][0] + bb.x, acc[rr][1] + bb.y,
                         acc[rr][2] + bb.z, acc[rr][3] + bb.w };
            *(float4*)&s_hg[(i0 + rr) * 128 + k0] = o;
        }
    }
    __syncthreads();

    // ---- layers ----
    #pragma unroll 1
    for (int l = 0; l < 2; l++) {
        const float* We1l = We1 + l * (257 * 128);
        const float* Wh1l = Wh1 + l * (256 * 128);

        // mi = hg @ Wa + be1
        stage_w(We1l, s_W, 16384);
        __syncthreads();
        {
            float acc[4][4] = {};
            gemm_block(s_hg, 128, s_W, 128, i0, k0, acc);
            float4 bb = *(const float4*)&be1[l * 128 + k0];
            #pragma unroll
            for (int rr = 0; rr < 4; rr++) {
                float4 o = { acc[rr][0] + bb.x, acc[rr][1] + bb.y,
                             acc[rr][2] + bb.z, acc[rr][3] + bb.w };
                *(float4*)&s_mi[(i0 + rr) * 128 + k0] = o;
            }
        }
        __syncthreads();

        // mj = hg @ Wb
        stage_w(We1l + 16384, s_W, 16384);
        __syncthreads();
        {
            float acc[4][4] = {};
            gemm_block(s_hg, 128, s_W, 128, i0, k0, acc);
            #pragma unroll
            for (int rr = 0; rr < 4; rr++) {
                float4 o = { acc[rr][0], acc[rr][1], acc[rr][2], acc[rr][3] };
                *(float4*)&s_mj[(i0 + rr) * 128 + k0] = o;
            }
        }
        __syncthreads();

        // stage We2 for the pair loop
        stage_w(We2 + l * 16384, s_W, 16384);
        __syncthreads();

        float4 wdv  = *(const float4*)&We1l[256 * 128 + k0];
        float4 be2v = *(const float4*)&be2[l * 128 + k0];
        float* m1w = s_m1 + warp * 512;
        int*   jlw = s_jl + warp * 32;

        // ---- sparse pair MLP + aggregation: each warp owns node i ----
        for (int i = warp; i < 32; i += 8) {
            float dlj = s_d2[i * 32 + lane];
            bool adj = (dlj < 1.0f) && (lane != i);
            unsigned msk = __ballot_sync(0xffffffffu, adj);
            int nj = __popc(msk);
            if (adj) jlw[__popc(msk & ((1u << lane) - 1u))] = lane;
            __syncwarp();

            float4 miv = *(const float4*)&s_mi[i * 128 + k0];
            float a0 = 0.f, a1 = 0.f, a2 = 0.f, a3 = 0.f;

            for (int base = 0; base < nj; base += 4) {
                // build up to 4 rows of m1 = silu(mi[i] + mj[j] + d2*wd + be1)
                #pragma unroll
                for (int rr = 0; rr < 4; rr++) {
                    int r = base + rr;
                    float4 v = { 0.f, 0.f, 0.f, 0.f };
                    if (r < nj) {
                        int j = jlw[r];
                        float dd = s_d2[i * 32 + j];
                        float4 mjv = *(const float4*)&s_mj[j * 128 + k0];
                        v.x = silu_f(miv.x + mjv.x + dd * wdv.x);
                        v.y = silu_f(miv.y + mjv.y + dd * wdv.y);
                        v.z = silu_f(miv.z + mjv.z + dd * wdv.z);
                        v.w = silu_f(miv.w + mjv.w + dd * wdv.w);
                    }
                    *(float4*)&m1w[rr * 128 + k0] = v;
                }
                __syncwarp();

                float y[4][4] = {};
                gemm_block(m1w, 128, s_W, 128, 0, k0, y);
                __syncwarp();  // protect m1w before next chunk overwrites it

                #pragma unroll
                for (int rr = 0; rr < 4; rr++) {
                    if (base + rr < nj) {
                        a0 += silu_f(y[rr][0] + be2v.x);
                        a1 += silu_f(y[rr][1] + be2v.y);
                        a2 += silu_f(y[rr][2] + be2v.z);
                        a3 += silu_f(y[rr][3] + be2v.w);
                    }
                }
            }
            float4 o = { a0, a1, a2, a3 };
            *(float4*)&s_agg[i * 128 + k0] = o;
        }
        __syncthreads();

        // u = silu(hg @ Wh1a + agg @ Wh1b + bh1)  (acc persists across stages)
        stage_w(Wh1l, s_W, 16384);
        __syncthreads();
        float acc[4][4] = {};
        gemm_block(s_hg, 128, s_W, 128, i0, k0, acc);
        __syncthreads();
        stage_w(Wh1l + 16384, s_W, 16384);
        __syncthreads();
        gemm_block(s_agg, 128, s_W, 128, i0, k0, acc);
        {
            float4 bb = *(const float4*)&bh1[l * 128 + k0];
            #pragma unroll
            for (int rr = 0; rr < 4; rr++) {
                float4 o = { silu_f(acc[rr][0] + bb.x), silu_f(acc[rr][1] + bb.y),
                             silu_f(acc[rr][2] + bb.z), silu_f(acc[rr][3] + bb.w) };
                *(float4*)&s_mi[(i0 + rr) * 128 + k0] = o;  // reuse s_mi as u
            }
        }
        __syncthreads();

        // hg += u @ Wh2 + bh2
        stage_w(Wh2 + l * 16384, s_W, 16384);
        __syncthreads();
        {
            float acc2[4][4] = {};
            gemm_block(s_mi, 128, s_W, 128, i0, k0, acc2);
            float4 bb = *(const float4*)&bh2[l * 128 + k0];
            #pragma unroll
            for (int rr = 0; rr < 4; rr++) {
                float4 cur = *(float4*)&s_hg[(i0 + rr) * 128 + k0];
                cur.x += acc2[rr][0] + bb.x;
                cur.y += acc2[rr][1] + bb.y;
                cur.z += acc2[rr][2] + bb.z;
                cur.w += acc2[rr][3] + bb.w;
                *(float4*)&s_hg[(i0 + rr) * 128 + k0] = cur;
            }
        }
        __syncthreads();
    }

    // ---- head: ho = hg @ W_out + b_out ----
    stage_w(W_out, s_W, 16384);
    __syncthreads();
    {
        float acc[4][4] = {};
        gemm_block(s_hg, 128, s_W, 128, i0, k0, acc);
        float4 bb = *(const float4*)&b_out[k0];
        #pragma unroll
        for (int rr = 0; rr < 4; rr++) {
            float4 o = { acc[rr][0] + bb.x, acc[rr][1] + bb.y,
                         acc[rr][2] + bb.z, acc[rr][3] + bb.w };
            *(float4*)&s_mj[(i0 + rr) * 128 + k0] = o;  // reuse s_mj as ho
        }
    }
    __syncthreads();

    // t1 = silu(ho @ Wn1 + bn1)
    stage_w(Wn1, s_W, 16384);
    __syncthreads();
    {
        float acc[4][4] = {};
        gemm_block(s_mj, 128, s_W, 128, i0, k0, acc);
        float4 bb = *(const float4*)&bn1[k0];
        #pragma unroll
        for (int rr = 0; rr < 4; rr++) {
            float4 o = { silu_f(acc[rr][0] + bb.x), silu_f(acc[rr][1] + bb.y),
                         silu_f(acc[rr][2] + bb.z), silu_f(acc[rr][3] + bb.w) };
            *(float4*)&s_mi[(i0 + rr) * 128 + k0] = o;  // reuse s_mi as t1
        }
    }
    __syncthreads();

    // out[b] = sum_i (t1[i] . Wn2) + 32*bn2  = (colsum t1) . Wn2 + 32*bn2
    float part = 0.0f;
    if (tid < 128) {
        float s = 0.0f;
        #pragma unroll
        for (int i = 0; i < 32; i++) s += s_mi[i * 128 + tid];
        part = s * Wn2[tid];
    }
    #pragma unroll
    for (int off = 16; off > 0; off >>= 1)
        part += __shfl_down_sync(0xffffffffu, part, off);
    if (warp < 4 && lane == 0) s_red[warp] = part;
    __syncthreads();
    if (tid == 0)
        g_out[b] = s_red[0] + s_red[1] + s_red[2] + s_red[3] + 32.0f * bn2[0];
}

extern "C" void kernel_launch(void* const* d_in, const int* in_sizes, int n_in,
                              void* d_out, int out_size) {
    const float* g_h   = (const float*)d_in[0];
    const float* g_x   = (const float*)d_in[1];
    // d_in[2] = batch indices: layout is repeat(arange(B), M); implicit here.
    const float* W_in  = (const float*)d_in[3];
    const float* b_in  = (const float*)d_in[4];
    const float* We1   = (const float*)d_in[5];
    const float* be1   = (const float*)d_in[6];
    const float* We2   = (const float*)d_in[7];
    const float* be2   = (const float*)d_in[8];
    const float* Wh1   = (const float*)d_in[9];
    const float* bh1   = (const float*)d_in[10];
    const float* Wh2   = (const float*)d_in[11];
    const float* bh2   = (const float*)d_in[12];
    const float* W_out = (const float*)d_in[13];
    const float* b_out = (const float*)d_in[14];
    const float* Wn1   = (const float*)d_in[15];
    const float* bn1   = (const float*)d_in[16];
    const float* Wn2   = (const float*)d_in[17];
    const float* bn2   = (const float*)d_in[18];
    float* out = (float*)d_out;

    const int smem_bytes = 38760 * 4;
    cudaFuncSetAttribute(sake_kernel, cudaFuncAttributeMaxDynamicSharedMemorySize,
                         smem_bytes);
    sake_kernel<<<NB, 256, smem_bytes>>>(
        g_h, g_x, W_in, b_in, We1, be1, We2, be2, Wh1, bh1, Wh2, bh2,
        W_out, b_out, Wn1, bn1, Wn2, bn2, out);
}